// round 8
// baseline (speedup 1.0000x reference)
#include <cuda_runtime.h>
#include <cstdint>

// out[m][d] = sum_k x[m][k] * W[k][d];  M=8192, K=4096, N=32, fp32.
//
// bf16x3 split GEMM on mma.sync (tcgen05 rejected by harness sm_103 target).
//   D += Ahi*Bhi + Ahi*Blo + Alo*Bhi  (fp32 accum), rel_err ~5e-6.
//
// R7: evidence across R2-R6 says B-via-LDG thrashes the per-SM L1tex queue as
// CTA count grows; the only sub-40us gemm (R3, ~38us) served B from smem.
// So: B = per-CTA smem fragment table (LDS.128, swizzled conflict-free),
// A = direct k-permuted LDG.128 (R4 shape), 1024 CTAs, single kernel
// (table build replaces the wsplit launch), fused deterministic reduction.

#define M_TOTAL 8192
#define K_TOTAL 4096
#define N_OUT   32
#define KSPLIT  16
#define KPER    (K_TOTAL / KSPLIT)     // 256
#define NIT     (KPER / 16)            // 16 k-steps per CTA
#define WARPS_CTA 4
#define THREADS  (WARPS_CTA * 32)
#define MB_ROWS  128
#define NMB      (M_TOTAL / MB_ROWS)   // 64
#define NCTA     (NMB * KSPLIT)        // 1024
#define NBENT    (NIT * 4 * 2 * 8)     // 1024 table entries (uint4)

__device__ float g_part[(size_t)KSPLIT * M_TOTAL * N_OUT];  // 16 MB (L2)
__device__ int   g_cnt[NMB];

__device__ __forceinline__ void split2(float f0, float f1,
                                       uint32_t& hp, uint32_t& lp) {
    asm("cvt.rn.bf16x2.f32 %0, %1, %2;" : "=r"(hp) : "f"(f1), "f"(f0));
    float h0 = __uint_as_float(hp << 16);
    float h1 = __uint_as_float(hp & 0xffff0000u);
    float g0 = f0 - h0, g1 = f1 - h1;
    asm("cvt.rn.bf16x2.f32 %0, %1, %2;" : "=r"(lp) : "f"(g1), "f"(g0));
}

__device__ __forceinline__ void mma16816(float* d, const uint32_t* a,
                                         uint32_t b0, uint32_t b1) {
    asm volatile(
        "mma.sync.aligned.m16n8k16.row.col.f32.bf16.bf16.f32 "
        "{%0,%1,%2,%3}, {%4,%5,%6,%7}, {%8,%9}, {%0,%1,%2,%3};"
        : "+f"(d[0]), "+f"(d[1]), "+f"(d[2]), "+f"(d[3])
        : "r"(a[0]), "r"(a[1]), "r"(a[2]), "r"(a[3]), "r"(b0), "r"(b1));
}

// smem table index for entry (st, c, h, r); swizzle r' = (r + 2c) & 7 keeps
// every LDS.128 8-lane phase on 8 distinct 16B banks-groups.
__device__ __forceinline__ int uidx(int st, int c, int h, int r) {
    return ((st * 4 + c) * 2 + h) * 8 + ((r + 2 * c) & 7);
}

struct AF { float4 p[2][2]; };          // [mtile][row r / r+8]

__global__ void __launch_bounds__(THREADS, 6)
gemm_hmma_kernel(const float* __restrict__ x, const float* __restrict__ w,
                 float* __restrict__ out) {
    __shared__ __align__(16) uint4 sBhi[NBENT];   // 16 KB
    __shared__ __align__(16) uint4 sBlo[NBENT];   // 16 KB

    const int tid  = threadIdx.x;
    const int wid  = tid >> 5, lane = tid & 31;
    const int mb   = blockIdx.x & (NMB - 1);
    const int kp   = blockIdx.x >> 6;
    const int k0   = kp * KPER;
    const int m0   = mb * MB_ROWS + wid * 32;
    const int r    = lane >> 2;
    const int c    = lane & 3;

    // ---- build B fragment table from (L2-hot) W: 8 entries per thread ----
    #pragma unroll
    for (int q = 0; q < NBENT / THREADS; q++) {
        const int e  = q * THREADS + tid;
        const int er = e & 7, eh = (e >> 3) & 1, ec = (e >> 4) & 3, es = e >> 6;
        const int k  = k0 + es * 16 + ec * 4 + eh * 2;
        uint32_t hi[4], lo[4];
        #pragma unroll
        for (int j = 0; j < 4; j++) {
            const int n = j * 8 + er;
            split2(w[(size_t)k * N_OUT + n], w[(size_t)(k + 1) * N_OUT + n],
                   hi[j], lo[j]);
        }
        const int u = uidx(es, ec, eh, er);
        sBhi[u] = make_uint4(hi[0], hi[1], hi[2], hi[3]);
        sBlo[u] = make_uint4(lo[0], lo[1], lo[2], lo[3]);
    }
    __syncthreads();

    const float* xa = x + (size_t)m0 * K_TOTAL + k0;

    auto load_a = [&](int it, AF& a) {
        const int col = it * 16 + c * 4;
        #pragma unroll
        for (int i = 0; i < 2; i++) {
            a.p[i][0] = *(const float4*)(xa + (size_t)(i * 16 + r)     * K_TOTAL + col);
            a.p[i][1] = *(const float4*)(xa + (size_t)(i * 16 + r + 8) * K_TOTAL + col);
        }
    };

    float d[2][4][4];
    #pragma unroll
    for (int i = 0; i < 2; i++)
        #pragma unroll
        for (int j = 0; j < 4; j++)
            #pragma unroll
            for (int q = 0; q < 4; q++) d[i][j][q] = 0.f;

    const int ubase = uidx(0, c, 0, r);   // step/h strides: +64 / +8 words

    auto step = [&](const AF& a, int it) {
        // B fragments: 4 conflict-free LDS.128
        const int u = ubase + it * 64;
        const uint4 h0 = sBhi[u], h1 = sBhi[u + 8];
        const uint4 l0 = sBlo[u], l1 = sBlo[u + 8];
        uint32_t ahi[2][4], alo[2][4];
        #pragma unroll
        for (int i = 0; i < 2; i++) {
            split2(a.p[i][0].x, a.p[i][0].y, ahi[i][0], alo[i][0]);
            split2(a.p[i][1].x, a.p[i][1].y, ahi[i][1], alo[i][1]);
            split2(a.p[i][0].z, a.p[i][0].w, ahi[i][2], alo[i][2]);
            split2(a.p[i][1].z, a.p[i][1].w, ahi[i][3], alo[i][3]);
        }
        const uint32_t* bh0 = &h0.x; const uint32_t* bh1 = &h1.x;
        const uint32_t* bl0 = &l0.x; const uint32_t* bl1 = &l1.x;
        #pragma unroll
        for (int i = 0; i < 2; i++)
            #pragma unroll
            for (int j = 0; j < 4; j++) {
                mma16816(d[i][j], ahi[i], bh0[j], bh1[j]);
                mma16816(d[i][j], ahi[i], bl0[j], bl1[j]);
                mma16816(d[i][j], alo[i], bh0[j], bh1[j]);
            }
    };

    AF a0, a1;
    load_a(0, a0);
    #pragma unroll 1
    for (int it = 0; it < NIT; it += 2) {
        const int n1 = (it + 1 < NIT) ? it + 1 : it;
        load_a(n1, a1);
        step(a0, it);
        const int n2 = (it + 2 < NIT) ? it + 2 : it;
        load_a(n2, a0);
        step(a1, n1);
    }

    // ---- store partials ----
    float* base = g_part + ((size_t)kp * M_TOTAL + m0) * N_OUT;
    #pragma unroll
    for (int i = 0; i < 2; i++)
        #pragma unroll
        for (int j = 0; j < 4; j++) {
            const int col = j * 8 + c * 2;
            *(float2*)(base + (size_t)(i * 16 + r)     * N_OUT + col) =
                make_float2(d[i][j][0], d[i][j][1]);
            *(float2*)(base + (size_t)(i * 16 + r + 8) * N_OUT + col) =
                make_float2(d[i][j][2], d[i][j][3]);
        }

    // ---- deterministic fused reduction (last CTA per m-block) ----
    __shared__ int s_last;
    __threadfence();
    __syncthreads();
    if (tid == 0) {
        s_last = (atomicAdd(&g_cnt[mb], 1) == KSPLIT - 1);
        if (s_last) __threadfence();
    }
    __syncthreads();
    if (s_last) {
        const int nf4 = MB_ROWS * N_OUT / 4;              // 1024 float4
        const float4* sc = (const float4*)g_part;
        float4* dst = (float4*)out + (size_t)mb * nf4;
        #pragma unroll 1
        for (int q = tid; q < nf4; q += THREADS) {
            const size_t o = (size_t)mb * nf4 + q;
            float4 sv = make_float4(0.f, 0.f, 0.f, 0.f);
            #pragma unroll 1
            for (int g = 0; g < 2; g++) {           // two batches of 8 (MLP 8)
                float4 v[8];
                #pragma unroll
                for (int p = 0; p < 8; p++)
                    v[p] = sc[(size_t)(g * 8 + p) * (M_TOTAL * N_OUT / 4) + o];
                #pragma unroll
                for (int p = 0; p < 8; p++) {       // fixed order: deterministic
                    sv.x += v[p].x; sv.y += v[p].y;
                    sv.z += v[p].z; sv.w += v[p].w;
                }
            }
            dst[q] = sv;
        }
        if (tid == 0) g_cnt[mb] = 0;   // reset for graph replay
    }
}

extern "C" void kernel_launch(void* const* d_in, const int* in_sizes, int n_in,
                              void* d_out, int out_size) {
    const float* x = (const float*)d_in[0];   // [8192, 4096]
    const float* w = (const float*)d_in[1];   // [4096, 32]
    float* out = (float*)d_out;               // [8192, 32]

    gemm_hmma_kernel<<<NCTA, THREADS>>>(x, w, out);
}

// round 9
// speedup vs baseline: 1.7709x; 1.7709x over previous
#include <cuda_runtime.h>
#include <cstdint>

// out[m][d] = sum_k x[m][k] * W[k][d];  M=8192, K=4096, N=32, fp32.
//
// bf16x3 split GEMM on mma.sync (tcgen05 rejected by harness sm_103 target).
//   D += Ahi*Bhi + Ahi*Blo + Alo*Bhi  (fp32 accum), rel_err ~5e-6.
//
// R8 = R4 (best proven, 45.1us) + prefetch.global.L2 for A two load-iterations
// ahead. R6/R7 showed reg-capping + more CTAs regress (spills); R4's balance
// of regs/warps/MLP is a local optimum, so the only free MLP is L2 prefetch:
// no registers, no warps, turns mainloop A DRAM misses (577cyc) into L2 hits
// (~250cyc).

#define M_TOTAL 8192
#define K_TOTAL 4096
#define N_OUT   32
#define KSPLIT  8
#define KPER    (K_TOTAL / KSPLIT)     // 512
#define NIT     (KPER / 16)            // 32 k-steps per CTA
#define NSTEPG  (K_TOTAL / 16)         // 256 global k-steps
#define WARPS_CTA 4
#define THREADS  (WARPS_CTA * 32)
#define MB_ROWS  128
#define NMB      (M_TOTAL / MB_ROWS)   // 64
#define NCTA     (NMB * KSPLIT)        // 512

__device__ float g_part[(size_t)KSPLIT * M_TOTAL * N_OUT];  // 8 MB (L2-hot)
__device__ uint4 g_whi2[NSTEPG * 4 * 8 * 2];                // 256 KB frag table
__device__ uint4 g_wlo2[NSTEPG * 4 * 8 * 2];                // 256 KB
__device__ int   g_cnt[NMB];                                // arrival counters

__device__ __forceinline__ void split2(float f0, float f1,
                                       uint32_t& hp, uint32_t& lp) {
    asm("cvt.rn.bf16x2.f32 %0, %1, %2;" : "=r"(hp) : "f"(f1), "f"(f0));
    float h0 = __uint_as_float(hp << 16);
    float h1 = __uint_as_float(hp & 0xffff0000u);
    float g0 = f0 - h0, g1 = f1 - h1;
    asm("cvt.rn.bf16x2.f32 %0, %1, %2;" : "=r"(lp) : "f"(g1), "f"(g0));
}

__device__ __forceinline__ void mma16816(float* d, const uint32_t* a,
                                         uint32_t b0, uint32_t b1) {
    asm volatile(
        "mma.sync.aligned.m16n8k16.row.col.f32.bf16.bf16.f32 "
        "{%0,%1,%2,%3}, {%4,%5,%6,%7}, {%8,%9}, {%0,%1,%2,%3};"
        : "+f"(d[0]), "+f"(d[1]), "+f"(d[2]), "+f"(d[3])
        : "r"(a[0]), "r"(a[1]), "r"(a[2]), "r"(a[3]), "r"(b0), "r"(b1));
}

__device__ __forceinline__ void pf_l2(const void* p) {
    asm volatile("prefetch.global.L2 [%0];" :: "l"(p));
}

// ---- W pre-split into fragment-ready uint4 tables ----
// widx(s,c,r,h) = ((s*4+c)*8+r)*2+h ; word j (j=0..3) is bf16x2 of
// W[k][j*8+r], W[k+1][j*8+r] with k = s*16 + c*4 + h*2.
__global__ void __launch_bounds__(128)
wsplit_kernel(const float* __restrict__ w) {
    const int t = blockIdx.x * 128 + threadIdx.x;       // 16384
    const int h = t & 1, r = (t >> 1) & 7, c = (t >> 4) & 3, s = t >> 6;
    const int k = s * 16 + c * 4 + h * 2;
    uint32_t hi[4], lo[4];
    #pragma unroll
    for (int j = 0; j < 4; j++) {
        const int n = j * 8 + r;
        split2(w[(size_t)k * N_OUT + n], w[(size_t)(k + 1) * N_OUT + n],
               hi[j], lo[j]);
    }
    g_whi2[t] = make_uint4(hi[0], hi[1], hi[2], hi[3]);
    g_wlo2[t] = make_uint4(lo[0], lo[1], lo[2], lo[3]);
}

struct AF { float4 p[2][2]; };          // [mtile][row r / r+8]
struct BF { uint4 h0, h1, l0, l1; };    // per-step B fragments

__global__ void __launch_bounds__(THREADS)
gemm_hmma_kernel(const float* __restrict__ x, float* __restrict__ out) {
    const int tid  = threadIdx.x;
    const int wid  = tid >> 5, lane = tid & 31;
    const int mb   = blockIdx.x & (NMB - 1);
    const int kp   = blockIdx.x >> 6;
    const int m0   = mb * MB_ROWS + wid * 32;
    const int r    = lane >> 2;
    const int c    = lane & 3;

    const float* xa = x + (size_t)m0 * K_TOTAL;
    const size_t bb = ((size_t)(kp * NIT) * 4 + c) * 16 + r * 2;

    // lane-private prefetch row: warp covers all 32 of its rows, one line each
    const float* xpf = x + (size_t)(m0 + lane) * K_TOTAL + kp * KPER;

    auto load_a = [&](int it, AF& a) {
        const int col = (kp * NIT + it) * 16 + c * 4;
        #pragma unroll
        for (int i = 0; i < 2; i++) {
            a.p[i][0] = *(const float4*)(xa + (size_t)(i * 16 + r)     * K_TOTAL + col);
            a.p[i][1] = *(const float4*)(xa + (size_t)(i * 16 + r + 8) * K_TOTAL + col);
        }
    };
    auto load_b = [&](int it, BF& b) {
        const size_t w = bb + (size_t)it * 64;
        b.h0 = g_whi2[w]; b.h1 = g_whi2[w + 1];
        b.l0 = g_wlo2[w]; b.l1 = g_wlo2[w + 1];
    };

    float d[2][4][4];
    #pragma unroll
    for (int i = 0; i < 2; i++)
        #pragma unroll
        for (int j = 0; j < 4; j++)
            #pragma unroll
            for (int q = 0; q < 4; q++) d[i][j][q] = 0.f;

    auto step = [&](const AF& a, const BF& b) {
        uint32_t ahi[2][4], alo[2][4];
        #pragma unroll
        for (int i = 0; i < 2; i++) {
            split2(a.p[i][0].x, a.p[i][0].y, ahi[i][0], alo[i][0]);
            split2(a.p[i][1].x, a.p[i][1].y, ahi[i][1], alo[i][1]);
            split2(a.p[i][0].z, a.p[i][0].w, ahi[i][2], alo[i][2]);
            split2(a.p[i][1].z, a.p[i][1].w, ahi[i][3], alo[i][3]);
        }
        const uint32_t* h0 = &b.h0.x;  const uint32_t* h1 = &b.h1.x;
        const uint32_t* l0 = &b.l0.x;  const uint32_t* l1 = &b.l1.x;
        #pragma unroll
        for (int i = 0; i < 2; i++)
            #pragma unroll
            for (int j = 0; j < 4; j++) {
                mma16816(d[i][j], ahi[i], h0[j], h1[j]);
                mma16816(d[i][j], ahi[i], l0[j], l1[j]);
                mma16816(d[i][j], alo[i], h0[j], h1[j]);
            }
    };

    AF a0, a1; BF b0, b1;
    // prologue prefetch: lines for steps 2-3 and 4-5 (one line = 2 steps)
    pf_l2(xpf + 2 * 16);
    pf_l2(xpf + 4 * 16);
    load_a(0, a0); load_b(0, b0);
    #pragma unroll 1
    for (int it = 0; it < NIT; it += 2) {
        // prefetch the 128B line holding steps it+4 / it+5 (all 32 warp rows)
        if (it + 4 < NIT) pf_l2(xpf + (it + 4) * 16);
        const int n1 = (it + 1 < NIT) ? it + 1 : it;
        load_a(n1, a1); load_b(n1, b1);
        step(a0, b0);
        const int n2 = (it + 2 < NIT) ? it + 2 : it;
        load_a(n2, a0); load_b(n2, b0);
        step(a1, b1);
    }

    // ---- store partials ----
    float* base = g_part + ((size_t)kp * M_TOTAL + m0) * N_OUT;
    #pragma unroll
    for (int i = 0; i < 2; i++)
        #pragma unroll
        for (int j = 0; j < 4; j++) {
            const int col = j * 8 + c * 2;
            *(float2*)(base + (size_t)(i * 16 + r)     * N_OUT + col) =
                make_float2(d[i][j][0], d[i][j][1]);
            *(float2*)(base + (size_t)(i * 16 + r + 8) * N_OUT + col) =
                make_float2(d[i][j][2], d[i][j][3]);
        }

    // ---- deterministic fused reduction (last CTA per m-block) ----
    __shared__ int s_last;
    __threadfence();
    __syncthreads();
    if (tid == 0) {
        s_last = (atomicAdd(&g_cnt[mb], 1) == KSPLIT - 1);
        if (s_last) __threadfence();
    }
    __syncthreads();
    if (s_last) {
        const int nf4 = MB_ROWS * N_OUT / 4;              // 1024 float4
        const float4* sc = (const float4*)g_part;
        float4* dst = (float4*)out + (size_t)mb * nf4;
        #pragma unroll 1
        for (int q = tid; q < nf4; q += THREADS) {
            const size_t o = (size_t)mb * nf4 + q;
            float4 v[KSPLIT];
            #pragma unroll
            for (int p = 0; p < KSPLIT; p++)
                v[p] = sc[(size_t)p * (M_TOTAL * N_OUT / 4) + o];
            float4 sv = v[0];
            #pragma unroll
            for (int p = 1; p < KSPLIT; p++) {
                sv.x += v[p].x; sv.y += v[p].y;
                sv.z += v[p].z; sv.w += v[p].w;
            }
            dst[q] = sv;
        }
        if (tid == 0) g_cnt[mb] = 0;   // reset for graph replay
    }
}

extern "C" void kernel_launch(void* const* d_in, const int* in_sizes, int n_in,
                              void* d_out, int out_size) {
    const float* x = (const float*)d_in[0];   // [8192, 4096]
    const float* w = (const float*)d_in[1];   // [4096, 32]
    float* out = (float*)d_out;               // [8192, 32]

    wsplit_kernel<<<NSTEPG * 4 * 8 * 2 / 128, 128>>>(w);
    gemm_hmma_kernel<<<NCTA, THREADS>>>(x, out);
}